// round 16
// baseline (speedup 1.0000x reference)
#include <cuda_runtime.h>
#include <cstdint>

#define D_MODEL 1024
#define SEQ     2048
#define BATCH   2
#define NH      16
#define DH      64
#define M_TOT   (BATCH * SEQ)   // 4096 rows

// Scratch (allocation-free rule: __device__ globals)
__device__ float g_qkv  [(size_t)M_TOT * 3 * D_MODEL];     // [4096, 3072] tf32-rounded
__device__ float g_attn [(size_t)M_TOT * D_MODEL];         // [4096, 1024] tf32-rounded
__device__ float g_wqkvT[(size_t)3 * D_MODEL * D_MODEL];   // [3072, 1024] tf32
__device__ float g_woutT[(size_t)D_MODEL * D_MODEL];       // [1024, 1024] tf32

// ===========================================================================
// Helpers
// ===========================================================================
__device__ __forceinline__ uint32_t smem_u32(const void* p) {
    uint32_t a;
    asm("{ .reg .u64 t; cvta.to.shared.u64 t, %1; cvt.u32.u64 %0, t; }"
        : "=r"(a) : "l"(p));
    return a;
}
__device__ __forceinline__ float to_tf32(float x) {
    uint32_t u;
    asm("cvt.rna.tf32.f32 %0, %1;" : "=r"(u) : "f"(x));
    return __uint_as_float(u);
}
__device__ __forceinline__ uint32_t tf32bits(float x) {
    uint32_t u;
    asm("cvt.rna.tf32.f32 %0, %1;" : "=r"(u) : "f"(x));
    return u;
}
__device__ __forceinline__ float ex2f(float x) {
    float r;
    asm("ex2.approx.f32 %0, %1;" : "=f"(r) : "f"(x));
    return r;
}

#define CP_ASYNC16(saddr, gptr) \
    asm volatile("cp.async.cg.shared.global [%0], [%1], 16;" \
                 :: "r"(saddr), "l"(gptr) : "memory")
#define CP_COMMIT() asm volatile("cp.async.commit_group;" ::: "memory")

// D(16x8) += A(16x8, row) * B(8x8, col)  tf32 inputs, fp32 accumulate
#define MMA_TF32(c, a, b) \
    asm volatile("mma.sync.aligned.m16n8k8.row.col.f32.tf32.tf32.f32 " \
        "{%0,%1,%2,%3}, {%4,%5,%6,%7}, {%8,%9}, {%0,%1,%2,%3};" \
        : "+f"((c)[0]), "+f"((c)[1]), "+f"((c)[2]), "+f"((c)[3]) \
        : "r"((a)[0]), "r"((a)[1]), "r"((a)[2]), "r"((a)[3]), \
          "r"((b)[0]), "r"((b)[1]))

// ldmatrix x4: on 32-bit data, matrix j gives thread l the element at
// (row l/4, col l%4) of an 8x4 fp32 tile whose 8 row addresses come from
// lanes 8j..8j+7.
#define LDSM4(r0, r1, r2, r3, addr) \
    asm volatile("ldmatrix.sync.aligned.m8n8.x4.shared.b16 {%0,%1,%2,%3}, [%4];" \
        : "=r"(r0), "=r"(r1), "=r"(r2), "=r"(r3) : "r"(addr))

// ===========================================================================
// Transpose + tf32 round: out[C,R] = tf32(in[R,C]^T)
// ===========================================================================
__global__ void transpose_k(const float* __restrict__ in, float* __restrict__ out,
                            int R, int C)
{
    __shared__ float t[32][33];
    int tx = threadIdx.x, ty = threadIdx.y;
    int c0 = blockIdx.x * 32, r0 = blockIdx.y * 32;
    #pragma unroll
    for (int j = 0; j < 4; j++)
        t[ty + 8 * j][tx] = in[(size_t)(r0 + ty + 8 * j) * C + c0 + tx];
    __syncthreads();
    #pragma unroll
    for (int j = 0; j < 4; j++)
        out[(size_t)(c0 + ty + 8 * j) * R + r0 + tx] = to_tf32(t[tx][ty + 8 * j]);
}

// ===========================================================================
// mma.sync tf32 GEMM + bias (proven R14 kernel, unchanged).
// ===========================================================================
#define KS       32
#define ASTRIDE  36
#define AROWB    (ASTRIDE * 4)
#define TILE_F   (128 * ASTRIDE)
#define TILE_BB  (TILE_F * 4)
#define STAGE_B  (2 * TILE_BB)
#define GEMM_SMEM (2 * STAGE_B)           // 73728 B

__device__ __forceinline__ void stage_load(uint32_t sA, uint32_t sB,
                                           const float* ga, const float* gb, int K)
{
    #pragma unroll
    for (int it = 0; it < 4; it++) {
        CP_ASYNC16(sA + it * 32 * AROWB, ga + (size_t)(32 * it) * K);
        CP_ASYNC16(sB + it * 32 * AROWB, gb + (size_t)(32 * it) * K);
    }
    CP_COMMIT();
}

template<bool RNDOUT, bool RNDA>
__global__ __launch_bounds__(256, 2) void gemm_tc(
    const float* __restrict__ A, const float* __restrict__ Bt,
    const float* __restrict__ bias, float* __restrict__ C,
    int N, int K)
{
    extern __shared__ float smf[];
    const uint32_t sbase = smem_u32(smf);

    const int tid  = threadIdx.x;
    const int wid  = tid >> 5;
    const int lane = tid & 31;
    const int grp  = lane >> 2;
    const int qd   = lane & 3;
    const int wm   = wid & 3;
    const int wn   = wid >> 2;
    const int m0   = blockIdx.y * 128;
    const int n0   = blockIdx.x * 128;

    const int mi = lane >> 3;
    const int r8 = lane & 7;
    uint32_t aOff[2], bOff[4];
    #pragma unroll
    for (int mb = 0; mb < 2; mb++)
        aOff[mb] = ((wm * 32 + mb * 16 + (mi & 1) * 8 + r8) * ASTRIDE
                    + (mi >> 1) * 4) * 4;
    #pragma unroll
    for (int p = 0; p < 4; p++)
        bOff[p] = ((wn * 64 + (2 * p + (mi >> 1)) * 8 + r8) * ASTRIDE
                   + (mi & 1) * 4) * 4 + TILE_BB;

    const float* Ag = A  + (size_t)(m0 + (tid >> 3)) * K + (tid & 7) * 4;
    const float* Bg = Bt + (size_t)(n0 + (tid >> 3)) * K + (tid & 7) * 4;
    const uint32_t dA = sbase + (tid >> 3) * AROWB + (tid & 7) * 16;
    const uint32_t dB = dA + TILE_BB;

    const int NS = K / KS;

    float acc[2][8][4] = {};

    stage_load(dA, dB, Ag, Bg, K);
    stage_load(dA + STAGE_B, dB + STAGE_B, Ag + KS, Bg + KS, K);

    for (int s = 0; s < NS; s++) {
        if (s + 1 < NS) asm volatile("cp.async.wait_group 1;" ::: "memory");
        else            asm volatile("cp.async.wait_group 0;" ::: "memory");
        __syncthreads();

        const uint32_t sb = sbase + (s & 1) * STAGE_B;

        #pragma unroll
        for (int ks = 0; ks < 4; ks++) {
            uint32_t a[2][4], b[8][2];
            #pragma unroll
            for (int mb = 0; mb < 2; mb++) {
                LDSM4(a[mb][0], a[mb][1], a[mb][2], a[mb][3],
                      sb + aOff[mb] + ks * 32);
                if (RNDA) {
                    #pragma unroll
                    for (int j = 0; j < 4; j++)
                        a[mb][j] = tf32bits(__uint_as_float(a[mb][j]));
                }
            }
            #pragma unroll
            for (int p = 0; p < 4; p++)
                LDSM4(b[2 * p][0], b[2 * p][1], b[2 * p + 1][0], b[2 * p + 1][1],
                      sb + bOff[p] + ks * 32);
            #pragma unroll
            for (int mb = 0; mb < 2; mb++)
                #pragma unroll
                for (int nb = 0; nb < 8; nb++)
                    MMA_TF32(acc[mb][nb], a[mb], b[nb]);
        }
        __syncthreads();
        if (s + 2 < NS)
            stage_load(dA + ((s + 2) & 1) * STAGE_B, dB + ((s + 2) & 1) * STAGE_B,
                       Ag + (size_t)(s + 2) * KS, Bg + (size_t)(s + 2) * KS, K);
    }

    const float* brow = bias + n0 + wn * 64;
    #pragma unroll
    for (int mb = 0; mb < 2; mb++) {
        #pragma unroll
        for (int half = 0; half < 2; half++) {
            const int row = m0 + wm * 32 + mb * 16 + grp + half * 8;
            float* crow = C + (size_t)row * N + n0 + wn * 64;
            #pragma unroll
            for (int nb = 0; nb < 8; nb++) {
                float2 bb = *(const float2*)(brow + nb * 8 + 2 * qd);
                float2 o;
                o.x = acc[mb][nb][half * 2 + 0] + bb.x;
                o.y = acc[mb][nb][half * 2 + 1] + bb.y;
                if (RNDOUT) { o.x = to_tf32(o.x); o.y = to_tf32(o.y); }
                *(float2*)(crow + nb * 8 + 2 * qd) = o;
            }
        }
    }
}

// ===========================================================================
// Flash attention on mma.sync tf32 — R16: same plan as R15 but the P smem
// round-trip is done in TWO HALVES of 32 key-columns so the 16x36-stride
// per-warp buffer is never exceeded (R15's crash was P needing 64 cols in a
// 36-float row stride: writes/reads ran past the buffer and off the end of
// dynamic smem for the last warp).
// Smem (floats): Qs[128*68] | Ks[64*68] | Vs[2][64*72] | Ps[8][16*36]
//   = 8704 + 4352 + 9216 + 4608 = 26880 floats = 107520 B -> 2 CTAs/SM.
// Bank proofs: Q/K ldmatrix rows stride 68 = 4 mod 32 -> 16B phases 17r%8
//   distinct; P rows stride 36 -> phases 9r%8 distinct; P STS.64 banks
//   4grp+2qd(+1) cover all 32; V LDS banks 8qd+grp clean.
// ===========================================================================
#define ATTN_SMEM 107520

__global__ __launch_bounds__(256, 2) void attn_tc(
    const float* __restrict__ qkv,   // [M_TOT, 3*D_MODEL] tf32-rounded
    float* __restrict__ out)         // [M_TOT, D_MODEL]
{
    extern __shared__ float sm[];
    float* Vs = sm + 13056;
    float* Ps = sm + 22272;

    const uint32_t sbase = smem_u32(sm);
    const uint32_t KsU = sbase + 8704u * 4u;
    const uint32_t VsU = sbase + 13056u * 4u;
    const uint32_t PsU = sbase + 22272u * 4u;

    const int tid  = threadIdx.x;
    const int wid  = tid >> 5;
    const int lane = tid & 31;
    const int grp  = lane >> 2;
    const int qd   = lane & 3;
    const int q0   = blockIdx.x * 128;
    const int hoff = blockIdx.y * DH;
    const int bT   = blockIdx.z * SEQ;

    const int lrow = tid >> 4;        // 0..15
    const int lch  = tid & 15;        // 16B chunk within 64-float row

    // ldmatrix per-lane addresses
    const int mi = lane >> 3;
    const int r8 = lane & 7;
    const uint32_t qAddr = sbase + ((16 * wid + (mi & 1) * 8 + r8) * 68
                                    + (mi >> 1) * 4) * 4;
    const uint32_t pAddr = PsU + wid * 2304u
                         + (((mi & 1) * 8 + r8) * 36 + (mi >> 1) * 4) * 4;
    uint32_t kOff[4];
    #pragma unroll
    for (int p = 0; p < 4; p++)
        kOff[p] = (((2 * p + (mi >> 1)) * 8 + r8) * 68 + (mi & 1) * 4) * 4;

    // ---- staging lambdas (all threads participate; one commit each) ----
    auto stage_K = [&](int k0) {
        const float* kg = qkv + (size_t)(bT + k0 + lrow) * 3072 + 1024 + hoff + lch * 4;
        uint32_t dk = KsU + lrow * 272u + lch * 16u;
        #pragma unroll
        for (int it = 0; it < 4; it++)
            CP_ASYNC16(dk + it * 16 * 272, kg + (size_t)it * 16 * 3072);
        CP_COMMIT();
    };
    auto stage_V = [&](int p, int k0) {
        const float* vg = qkv + (size_t)(bT + k0 + lrow) * 3072 + 2048 + hoff + lch * 4;
        uint32_t dv = VsU + (uint32_t)p * 18432u + lrow * 288u + lch * 16u;
        #pragma unroll
        for (int it = 0; it < 4; it++)
            CP_ASYNC16(dv + it * 16 * 288, vg + (size_t)it * 16 * 3072);
        CP_COMMIT();
    };

    stage_K(0);
    stage_V(0, 0);
    stage_V(1, 64);

    // ---- load Q tile (128 x 64), scale*log2(e) folded in ----
    const float c1 = 0.18033688011112042f;   // (1/8) * log2(e)
    #pragma unroll
    for (int it = 0; it < 8; it++) {
        int row = lrow + 16 * it;
        float4 v = *(const float4*)(qkv + (size_t)(bT + q0 + row) * 3072 + hoff + lch * 4);
        v.x *= c1; v.y *= c1; v.z *= c1; v.w *= c1;
        *(float4*)(&sm[row * 68 + lch * 4]) = v;
    }

    float m0 = -1e30f, m1 = -1e30f, l0 = 0.f, l1 = 0.f;
    float o[8][4] = {};

    const int NT = SEQ / 64;
    for (int kt = 0; kt < NT; kt++) {
        const int p = kt & 1;
        // K(kt) and V(kt) must have landed; newest group (V(kt+1)) may pend.
        if (kt + 1 < NT) asm volatile("cp.async.wait_group 1;" ::: "memory");
        else             asm volatile("cp.async.wait_group 0;" ::: "memory");
        __syncthreads();

        // ---- S = Q K^T : fragments via ldmatrix (K single buffer) ----
        float s[8][4] = {};
        #pragma unroll
        for (int kb = 0; kb < 8; kb++) {
            uint32_t a[4], b[8][2];
            LDSM4(a[0], a[1], a[2], a[3], qAddr + kb * 32);
            #pragma unroll
            for (int pp = 0; pp < 4; pp++)
                LDSM4(b[2 * pp][0], b[2 * pp][1], b[2 * pp + 1][0], b[2 * pp + 1][1],
                      KsU + kOff[pp] + kb * 32);
            #pragma unroll
            for (int nb = 0; nb < 8; nb++)
                MMA_TF32(s[nb], a, b[nb]);
        }

        __syncthreads();                       // everyone done reading Ks
        if (kt + 1 < NT) stage_K((kt + 1) * 64);

        // ---- online softmax (base-2, pre-scaled; rows grp / grp+8) ----
        float t0 = -1e30f, t1 = -1e30f;
        #pragma unroll
        for (int nb = 0; nb < 8; nb++) {
            t0 = fmaxf(t0, fmaxf(s[nb][0], s[nb][1]));
            t1 = fmaxf(t1, fmaxf(s[nb][2], s[nb][3]));
        }
        t0 = fmaxf(t0, __shfl_xor_sync(0xffffffffu, t0, 1));
        t0 = fmaxf(t0, __shfl_xor_sync(0xffffffffu, t0, 2));
        t1 = fmaxf(t1, __shfl_xor_sync(0xffffffffu, t1, 1));
        t1 = fmaxf(t1, __shfl_xor_sync(0xffffffffu, t1, 2));

        float mn0 = fmaxf(m0, t0), mn1 = fmaxf(m1, t1);
        float al0 = ex2f(m0 - mn0), al1 = ex2f(m1 - mn1);
        m0 = mn0; m1 = mn1;

        float rs0 = 0.f, rs1 = 0.f;
        #pragma unroll
        for (int nb = 0; nb < 8; nb++) {
            s[nb][0] = ex2f(s[nb][0] - mn0);
            s[nb][1] = ex2f(s[nb][1] - mn0);
            s[nb][2] = ex2f(s[nb][2] - mn1);
            s[nb][3] = ex2f(s[nb][3] - mn1);
            rs0 += s[nb][0] + s[nb][1];
            rs1 += s[nb][2] + s[nb][3];
        }
        rs0 += __shfl_xor_sync(0xffffffffu, rs0, 1);
        rs0 += __shfl_xor_sync(0xffffffffu, rs0, 2);
        rs1 += __shfl_xor_sync(0xffffffffu, rs1, 1);
        rs1 += __shfl_xor_sync(0xffffffffu, rs1, 2);
        l0 = l0 * al0 + rs0;
        l1 = l1 * al1 + rs1;

        #pragma unroll
        for (int nb = 0; nb < 8; nb++) {
            o[nb][0] *= al0; o[nb][1] *= al0;
            o[nb][2] *= al1; o[nb][3] *= al1;
        }

        // ---- O += P V, in two 32-key halves through the P smem buffer ----
        const float* vp = Vs + p * 4608 + qd * 72 + grp;
        float* Pw = Ps + wid * 576;
        #pragma unroll
        for (int h = 0; h < 2; h++) {
            #pragma unroll
            for (int j = 0; j < 4; j++) {
                const int nb = 4 * h + j;
                *(float2*)(&Pw[grp * 36 + 8 * j + 2 * qd])
                    = make_float2(s[nb][0], s[nb][1]);
                *(float2*)(&Pw[(grp + 8) * 36 + 8 * j + 2 * qd])
                    = make_float2(s[nb][2], s[nb][3]);
            }
            __syncwarp();
            #pragma unroll
            for (int j = 0; j < 4; j++) {
                const int kb = 4 * h + j;
                uint32_t a[4];
                LDSM4(a[0], a[1], a[2], a[3], pAddr + j * 32);
                const float* vpp = vp + kb * 576;
                #pragma unroll
                for (int nb = 0; nb < 8; nb++) {
                    uint32_t b[2];
                    b[0] = __float_as_uint(vpp[nb * 8]);
                    b[1] = __float_as_uint(vpp[nb * 8 + 288]);
                    MMA_TF32(o[nb], a, b);
                }
            }
            __syncwarp();                      // half h reads done before h+1 store
        }

        __syncthreads();                       // everyone done reading Vs[p]
        if (kt + 2 < NT) stage_V(p, (kt + 2) * 64);
    }

    // ---- normalize + tf32-round (GEMM2 input) + store ----
    const float inv0 = 1.0f / l0, inv1 = 1.0f / l1;
    const int r0 = bT + q0 + 16 * wid + grp;
    float* p0 = out + (size_t)r0 * D_MODEL + hoff + 2 * qd;
    float* p1 = p0 + (size_t)8 * D_MODEL;
    #pragma unroll
    for (int nb = 0; nb < 8; nb++) {
        float2 lo, hi;
        lo.x = to_tf32(o[nb][0] * inv0); lo.y = to_tf32(o[nb][1] * inv0);
        hi.x = to_tf32(o[nb][2] * inv1); hi.y = to_tf32(o[nb][3] * inv1);
        *(float2*)(p0 + 8 * nb) = lo;
        *(float2*)(p1 + 8 * nb) = hi;
    }
}

// ===========================================================================
// Launch
// ===========================================================================
extern "C" void kernel_launch(void* const* d_in, const int* in_sizes, int n_in,
                              void* d_out, int out_size)
{
    (void)in_sizes; (void)n_in; (void)out_size;
    const float* x    = (const float*)d_in[0];
    const float* Wqkv = (const float*)d_in[1];
    const float* bqkv = (const float*)d_in[2];
    const float* Wout = (const float*)d_in[3];
    const float* bout = (const float*)d_in[4];
    float* out = (float*)d_out;

    float *qkv, *attn, *wqkvT, *woutT;
    cudaGetSymbolAddress((void**)&qkv,   g_qkv);
    cudaGetSymbolAddress((void**)&attn,  g_attn);
    cudaGetSymbolAddress((void**)&wqkvT, g_wqkvT);
    cudaGetSymbolAddress((void**)&woutT, g_woutT);

    cudaFuncSetAttribute((const void*)gemm_tc<true, true>,
                         cudaFuncAttributeMaxDynamicSharedMemorySize, GEMM_SMEM);
    cudaFuncSetAttribute((const void*)gemm_tc<false, false>,
                         cudaFuncAttributeMaxDynamicSharedMemorySize, GEMM_SMEM);
    cudaFuncSetAttribute((const void*)attn_tc,
                         cudaFuncAttributeMaxDynamicSharedMemorySize, ATTN_SMEM);

    // transpose + tf32-round weights
    transpose_k<<<dim3((3 * D_MODEL) / 32, D_MODEL / 32), dim3(32, 8)>>>(
        Wqkv, wqkvT, D_MODEL, 3 * D_MODEL);
    transpose_k<<<dim3(D_MODEL / 32, D_MODEL / 32), dim3(32, 8)>>>(
        Wout, woutT, D_MODEL, D_MODEL);

    // GEMM1: qkv = tf32(x @ Wqkv + b)  (A rna-rounded in-register)
    gemm_tc<true, true><<<dim3((3 * D_MODEL) / 128, M_TOT / 128), 256, GEMM_SMEM>>>(
        x, wqkvT, bqkv, qkv, 3 * D_MODEL, D_MODEL);

    // Attention on tensor cores
    attn_tc<<<dim3(SEQ / 128, NH, BATCH), 256, ATTN_SMEM>>>(qkv, attn);

    // GEMM2: out = attn @ Wout + b (fp32 output)
    gemm_tc<false, false><<<dim3(D_MODEL / 128, M_TOT / 128), 256, GEMM_SMEM>>>(
        attn, woutT, bout, out, D_MODEL, D_MODEL);
}

// round 17
// speedup vs baseline: 1.7847x; 1.7847x over previous
#include <cuda_runtime.h>
#include <cuda_fp16.h>
#include <cstdint>

#define D_MODEL 1024
#define SEQ     2048
#define BATCH   2
#define NH      16
#define DH      64
#define M_TOT   (BATCH * SEQ)   // 4096 rows

// Scratch (allocation-free rule: __device__ globals)
__device__ __half g_qkvh [(size_t)M_TOT * 3 * D_MODEL];    // [4096, 3072] fp16
__device__ __half g_attnh[(size_t)M_TOT * D_MODEL];        // [4096, 1024] fp16
__device__ __half g_xh   [(size_t)M_TOT * D_MODEL];        // fp16 x
__device__ __half g_wqkvT[(size_t)3 * D_MODEL * D_MODEL];  // [3072, 1024] fp16
__device__ __half g_woutT[(size_t)D_MODEL * D_MODEL];      // [1024, 1024] fp16

// ===========================================================================
// Helpers
// ===========================================================================
__device__ __forceinline__ uint32_t smem_u32(const void* p) {
    uint32_t a;
    asm("{ .reg .u64 t; cvta.to.shared.u64 t, %1; cvt.u32.u64 %0, t; }"
        : "=r"(a) : "l"(p));
    return a;
}
__device__ __forceinline__ uint32_t pack_h2(float lo, float hi) {
    uint32_t r;
    asm("cvt.rn.f16x2.f32 %0, %1, %2;" : "=r"(r) : "f"(hi), "f"(lo));
    return r;
}
__device__ __forceinline__ float ex2f(float x) {
    float r;
    asm("ex2.approx.f32 %0, %1;" : "=f"(r) : "f"(x));
    return r;
}

#define CP_ASYNC16(saddr, gptr) \
    asm volatile("cp.async.cg.shared.global [%0], [%1], 16;" \
                 :: "r"(saddr), "l"(gptr) : "memory")
#define CP_COMMIT() asm volatile("cp.async.commit_group;" ::: "memory")

// D(16x8) += A(16x16, row) * B(16x8, col)  fp16 inputs, fp32 accumulate
#define MMA_F16(c, a, b) \
    asm volatile("mma.sync.aligned.m16n8k16.row.col.f32.f16.f16.f32 " \
        "{%0,%1,%2,%3}, {%4,%5,%6,%7}, {%8,%9}, {%0,%1,%2,%3};" \
        : "+f"((c)[0]), "+f"((c)[1]), "+f"((c)[2]), "+f"((c)[3]) \
        : "r"((a)[0]), "r"((a)[1]), "r"((a)[2]), "r"((a)[3]), \
          "r"((b)[0]), "r"((b)[1]))

#define LDSM4(r0, r1, r2, r3, addr) \
    asm volatile("ldmatrix.sync.aligned.m8n8.x4.shared.b16 {%0,%1,%2,%3}, [%4];" \
        : "=r"(r0), "=r"(r1), "=r"(r2), "=r"(r3) : "r"(addr))
#define LDSM4T(r0, r1, r2, r3, addr) \
    asm volatile("ldmatrix.sync.aligned.m8n8.x4.trans.shared.b16 {%0,%1,%2,%3}, [%4];" \
        : "=r"(r0), "=r"(r1), "=r"(r2), "=r"(r3) : "r"(addr))

// ===========================================================================
// x -> fp16 copy (8 floats / thread)
// ===========================================================================
__global__ void cvt_h(const float* __restrict__ in, __half* __restrict__ out)
{
    int i = (blockIdx.x * blockDim.x + threadIdx.x) * 8;
    float4 v0 = *(const float4*)(in + i);
    float4 v1 = *(const float4*)(in + i + 4);
    uint4 o;
    o.x = pack_h2(v0.x, v0.y); o.y = pack_h2(v0.z, v0.w);
    o.z = pack_h2(v1.x, v1.y); o.w = pack_h2(v1.z, v1.w);
    *(uint4*)(out + i) = o;
}

// ===========================================================================
// Transpose + fp16 round: out[C,R] = fp16(in[R,C]^T)
// ===========================================================================
__global__ void transpose_h(const float* __restrict__ in, __half* __restrict__ out,
                            int R, int C)
{
    __shared__ float t[32][33];
    int tx = threadIdx.x, ty = threadIdx.y;
    int c0 = blockIdx.x * 32, r0 = blockIdx.y * 32;
    #pragma unroll
    for (int j = 0; j < 4; j++)
        t[ty + 8 * j][tx] = in[(size_t)(r0 + ty + 8 * j) * C + c0 + tx];
    __syncthreads();
    #pragma unroll
    for (int j = 0; j < 4; j++)
        out[(size_t)(c0 + ty + 8 * j) * R + r0 + tx] = __float2half_rn(t[tx][ty + 8 * j]);
}

// ===========================================================================
// fp16 mma GEMM + bias: C[M,N] = A[M,K] @ Bt[N,K]^T + bias[N]
// A, Bt fp16. 128x128 CTA, 8 warps (4Mx2N), warp tile 32x64, m16n8k16.
// K staged 32 per cp.async group, double buffered, 2 k16-steps per stage.
// Smem rows 40 halves (80B): ldmatrix row phase 5r%8 distinct -> clean.
// ===========================================================================
#define KS       32                       // k elements per stage
#define ROWH     40                       // halves per smem row
#define ROWB     (ROWH * 2)               // 80 bytes
#define TILE_BB  (128 * ROWB)             // 10240 B per operand tile
#define STAGE_B  (2 * TILE_BB)            // 20480 B
#define GEMM_SMEM (2 * STAGE_B)           // 40960 B

__device__ __forceinline__ void stage_load_h(uint32_t sA, uint32_t sB,
                                             const __half* ga, const __half* gb, int K)
{
    #pragma unroll
    for (int it = 0; it < 2; it++) {
        CP_ASYNC16(sA + it * 64 * ROWB, ga + (size_t)(64 * it) * K);
        CP_ASYNC16(sB + it * 64 * ROWB, gb + (size_t)(64 * it) * K);
    }
    CP_COMMIT();
}

template<bool HALFOUT>
__global__ __launch_bounds__(256, 2) void gemm_h(
    const __half* __restrict__ A, const __half* __restrict__ Bt,
    const float* __restrict__ bias, void* __restrict__ Cv,
    int N, int K)
{
    extern __shared__ char smc[];
    const uint32_t sbase = smem_u32(smc);

    const int tid  = threadIdx.x;
    const int wid  = tid >> 5;
    const int lane = tid & 31;
    const int grp  = lane >> 2;
    const int qd   = lane & 3;
    const int wm   = wid & 3;
    const int wn   = wid >> 2;
    const int m0   = blockIdx.y * 128;
    const int n0   = blockIdx.x * 128;

    // ldmatrix per-lane byte offsets
    const int mi = lane >> 3;
    const int r8 = lane & 7;
    uint32_t aOff[2], bOff[4];
    #pragma unroll
    for (int mb = 0; mb < 2; mb++)
        aOff[mb] = ((wm * 32 + mb * 16 + (mi & 1) * 8 + r8) * ROWH
                    + (mi >> 1) * 8) * 2;
    #pragma unroll
    for (int p = 0; p < 4; p++)
        bOff[p] = ((wn * 64 + (2 * p + (mi >> 1)) * 8 + r8) * ROWH
                   + (mi & 1) * 8) * 2 + TILE_BB;

    // cp.async: thread covers row tid>>2 (+64), 16B chunk tid&3
    const __half* Ag = A  + (size_t)(m0 + (tid >> 2)) * K + (tid & 3) * 8;
    const __half* Bg = Bt + (size_t)(n0 + (tid >> 2)) * K + (tid & 3) * 8;
    const uint32_t dA = sbase + (tid >> 2) * ROWB + (tid & 3) * 16;
    const uint32_t dB = dA + TILE_BB;

    const int NS = K / KS;   // 32

    float acc[2][8][4] = {};

    stage_load_h(dA, dB, Ag, Bg, K);
    stage_load_h(dA + STAGE_B, dB + STAGE_B, Ag + KS, Bg + KS, K);

    for (int s = 0; s < NS; s++) {
        if (s + 1 < NS) asm volatile("cp.async.wait_group 1;" ::: "memory");
        else            asm volatile("cp.async.wait_group 0;" ::: "memory");
        __syncthreads();

        const uint32_t sb = sbase + (s & 1) * STAGE_B;

        #pragma unroll
        for (int ks = 0; ks < 2; ks++) {        // k16 steps
            uint32_t a[2][4], b[8][2];
            #pragma unroll
            for (int mb = 0; mb < 2; mb++)
                LDSM4(a[mb][0], a[mb][1], a[mb][2], a[mb][3],
                      sb + aOff[mb] + ks * 32);
            #pragma unroll
            for (int p = 0; p < 4; p++)
                LDSM4(b[2 * p][0], b[2 * p][1], b[2 * p + 1][0], b[2 * p + 1][1],
                      sb + bOff[p] + ks * 32);
            #pragma unroll
            for (int mb = 0; mb < 2; mb++)
                #pragma unroll
                for (int nb = 0; nb < 8; nb++)
                    MMA_F16(acc[mb][nb], a[mb], b[nb]);
        }
        __syncthreads();
        if (s + 2 < NS)
            stage_load_h(dA + ((s + 2) & 1) * STAGE_B, dB + ((s + 2) & 1) * STAGE_B,
                         Ag + (size_t)(s + 2) * KS, Bg + (size_t)(s + 2) * KS, K);
    }

    const float* brow = bias + n0 + wn * 64;
    #pragma unroll
    for (int mb = 0; mb < 2; mb++) {
        #pragma unroll
        for (int half = 0; half < 2; half++) {
            const int row = m0 + wm * 32 + mb * 16 + grp + half * 8;
            const int colb = n0 + wn * 64;
            #pragma unroll
            for (int nb = 0; nb < 8; nb++) {
                float2 bb = *(const float2*)(brow + nb * 8 + 2 * qd);
                float ox = acc[mb][nb][half * 2 + 0] + bb.x;
                float oy = acc[mb][nb][half * 2 + 1] + bb.y;
                if (HALFOUT) {
                    __half* C = (__half*)Cv;
                    *(uint32_t*)(C + (size_t)row * N + colb + nb * 8 + 2 * qd)
                        = pack_h2(ox, oy);
                } else {
                    float* C = (float*)Cv;
                    *(float2*)(C + (size_t)row * N + colb + nb * 8 + 2 * qd)
                        = make_float2(ox, oy);
                }
            }
        }
    }
}

// ===========================================================================
// Flash attention on fp16 mma (m16n8k16).
// CTA = 128 queries of one (b,h); 8 warps, one 16-query m16 strip each.
// Q held in registers as A-frags (loaded once via ldmatrix).
// K,V double-buffered 64-key tiles via cp.async (stride 72 halves = 144B:
// ldmatrix row phase 9r%8 distinct -> conflict-free; V read with
// ldmatrix.trans). P needs NO conversion: the S C-fragment packs directly
// into the PV A-fragment with cvt.rn.f16x2.
// Smem: Q 128x72 + (K,V) 2x2x64x72 halves = 55296 B -> 2 CTAs/SM.
// ===========================================================================
#define ATTN_SMEM 55296

__global__ __launch_bounds__(256, 2) void attn_h(
    const __half* __restrict__ qkv,  // [M_TOT, 3*D_MODEL] fp16
    __half* __restrict__ out)        // [M_TOT, D_MODEL] fp16
{
    extern __shared__ char smc[];
    const uint32_t sbase = smem_u32(smc);
    const uint32_t QsU = sbase;                    // 128*72*2 = 18432 B
    const uint32_t KsU = sbase + 18432u;           // 2 bufs * 9216 B
    const uint32_t VsU = sbase + 36864u;           // 2 bufs * 9216 B

    const int tid  = threadIdx.x;
    const int wid  = tid >> 5;
    const int lane = tid & 31;
    const int grp  = lane >> 2;
    const int qd   = lane & 3;
    const int q0   = blockIdx.x * 128;
    const int hoff = blockIdx.y * DH;              // halves
    const int bT   = blockIdx.z * SEQ;

    const int lrow = tid >> 3;        // 0..31
    const int lch  = tid & 7;         // 16B chunk within 64-half row

    // ldmatrix per-lane offsets
    const int mi = lane >> 3;
    const int r8 = lane & 7;
    const uint32_t qAddr = QsU + ((16 * wid + (mi & 1) * 8 + r8) * 72
                                  + (mi >> 1) * 8) * 2;
    uint32_t kOff[4], vOff[4];
    #pragma unroll
    for (int p = 0; p < 4; p++) {
        kOff[p] = (((2 * p + (mi >> 1)) * 8 + r8) * 72 + (mi & 1) * 8) * 2;
        vOff[p] = (((mi & 1) * 8 + r8) * 72 + (2 * p + (mi >> 1)) * 8) * 2;
    }

    // ---- staging (all threads; one commit per call) ----
    auto stage_Q = [&]() {
        #pragma unroll
        for (int it = 0; it < 4; it++) {
            int row = lrow + 32 * it;
            const __half* g = qkv + (size_t)(bT + q0 + row) * 3072 + hoff + lch * 8;
            CP_ASYNC16(QsU + row * 144 + lch * 16, g);
        }
        CP_COMMIT();
    };
    auto stage_KV = [&](int p, int k0) {
        #pragma unroll
        for (int it = 0; it < 2; it++) {
            int row = lrow + 32 * it;
            const __half* g = qkv + (size_t)(bT + k0 + row) * 3072 + 1024 + hoff + lch * 8;
            CP_ASYNC16(KsU + p * 9216 + row * 144 + lch * 16, g);
            CP_ASYNC16(VsU + p * 9216 + row * 144 + lch * 16, g + 1024);
        }
        CP_COMMIT();
    };

    stage_Q();
    stage_KV(0, 0);
    stage_KV(1, 64);

    // ---- Q A-fragments to registers (Q smem dead afterwards) ----
    uint32_t qf[4][4];
    asm volatile("cp.async.wait_group 2;" ::: "memory");
    __syncthreads();
    #pragma unroll
    for (int ks = 0; ks < 4; ks++)
        LDSM4(qf[ks][0], qf[ks][1], qf[ks][2], qf[ks][3], qAddr + ks * 32);

    float m0 = -1e30f, m1 = -1e30f, l0 = 0.f, l1 = 0.f;
    float o[8][4] = {};
    const float c1 = 0.18033688011112042f;   // (1/8) * log2(e)

    const int NT = SEQ / 64;
    for (int kt = 0; kt < NT; kt++) {
        const int p = kt & 1;
        if (kt + 1 < NT) asm volatile("cp.async.wait_group 1;" ::: "memory");
        else             asm volatile("cp.async.wait_group 0;" ::: "memory");
        __syncthreads();

        const uint32_t kbuf = KsU + p * 9216;
        const uint32_t vbuf = VsU + p * 9216;

        // ---- S = Q K^T : 4 k16-steps x 8 n-tiles ----
        float s[8][4] = {};
        #pragma unroll
        for (int ks = 0; ks < 4; ks++) {
            uint32_t b[8][2];
            #pragma unroll
            for (int pp = 0; pp < 4; pp++)
                LDSM4(b[2 * pp][0], b[2 * pp][1], b[2 * pp + 1][0], b[2 * pp + 1][1],
                      kbuf + kOff[pp] + ks * 32);
            #pragma unroll
            for (int nb = 0; nb < 8; nb++)
                MMA_F16(s[nb], qf[ks], b[nb]);
        }

        // ---- online softmax (base-2; rows grp / grp+8 live in quads) ----
        float t0 = -1e30f, t1 = -1e30f;
        #pragma unroll
        for (int nb = 0; nb < 8; nb++) {
            s[nb][0] *= c1; s[nb][1] *= c1; s[nb][2] *= c1; s[nb][3] *= c1;
            t0 = fmaxf(t0, fmaxf(s[nb][0], s[nb][1]));
            t1 = fmaxf(t1, fmaxf(s[nb][2], s[nb][3]));
        }
        t0 = fmaxf(t0, __shfl_xor_sync(0xffffffffu, t0, 1));
        t0 = fmaxf(t0, __shfl_xor_sync(0xffffffffu, t0, 2));
        t1 = fmaxf(t1, __shfl_xor_sync(0xffffffffu, t1, 1));
        t1 = fmaxf(t1, __shfl_xor_sync(0xffffffffu, t1, 2));

        float mn0 = fmaxf(m0, t0), mn1 = fmaxf(m1, t1);
        float al0 = ex2f(m0 - mn0), al1 = ex2f(m1 - mn1);
        m0 = mn0; m1 = mn1;

        float rs0 = 0.f, rs1 = 0.f;
        #pragma unroll
        for (int nb = 0; nb < 8; nb++) {
            s[nb][0] = ex2f(s[nb][0] - mn0);
            s[nb][1] = ex2f(s[nb][1] - mn0);
            s[nb][2] = ex2f(s[nb][2] - mn1);
            s[nb][3] = ex2f(s[nb][3] - mn1);
            rs0 += s[nb][0] + s[nb][1];
            rs1 += s[nb][2] + s[nb][3];
        }
        rs0 += __shfl_xor_sync(0xffffffffu, rs0, 1);
        rs0 += __shfl_xor_sync(0xffffffffu, rs0, 2);
        rs1 += __shfl_xor_sync(0xffffffffu, rs1, 1);
        rs1 += __shfl_xor_sync(0xffffffffu, rs1, 2);
        l0 = l0 * al0 + rs0;
        l1 = l1 * al1 + rs1;

        #pragma unroll
        for (int nb = 0; nb < 8; nb++) {
            o[nb][0] *= al0; o[nb][1] *= al0;
            o[nb][2] *= al1; o[nb][3] *= al1;
        }

        // ---- O += P V : P packs straight from S C-frags; V via ldsm.trans
        #pragma unroll
        for (int ks = 0; ks < 4; ks++) {       // 16-key blocks
            uint32_t a[4];
            a[0] = pack_h2(s[2 * ks][0],     s[2 * ks][1]);
            a[1] = pack_h2(s[2 * ks][2],     s[2 * ks][3]);
            a[2] = pack_h2(s[2 * ks + 1][0], s[2 * ks + 1][1]);
            a[3] = pack_h2(s[2 * ks + 1][2], s[2 * ks + 1][3]);
            uint32_t b[8][2];
            #pragma unroll
            for (int pp = 0; pp < 4; pp++)
                LDSM4T(b[2 * pp][0], b[2 * pp][1], b[2 * pp + 1][0], b[2 * pp + 1][1],
                       vbuf + vOff[pp] + ks * 16 * 144);
            #pragma unroll
            for (int nb = 0; nb < 8; nb++)
                MMA_F16(o[nb], a, b[nb]);
        }

        __syncthreads();
        if (kt + 2 < NT) stage_KV(p, (kt + 2) * 64);
    }

    // ---- normalize + fp16 store (GEMM2 input) ----
    const float inv0 = 1.0f / l0, inv1 = 1.0f / l1;
    const int r0 = bT + q0 + 16 * wid + grp;
    __half* p0 = out + (size_t)r0 * D_MODEL + hoff + 2 * qd;
    __half* p1 = p0 + (size_t)8 * D_MODEL;
    #pragma unroll
    for (int nb = 0; nb < 8; nb++) {
        *(uint32_t*)(p0 + 8 * nb) = pack_h2(o[nb][0] * inv0, o[nb][1] * inv0);
        *(uint32_t*)(p1 + 8 * nb) = pack_h2(o[nb][2] * inv1, o[nb][3] * inv1);
    }
}

// ===========================================================================
// Launch
// ===========================================================================
extern "C" void kernel_launch(void* const* d_in, const int* in_sizes, int n_in,
                              void* d_out, int out_size)
{
    (void)in_sizes; (void)n_in; (void)out_size;
    const float* x    = (const float*)d_in[0];
    const float* Wqkv = (const float*)d_in[1];
    const float* bqkv = (const float*)d_in[2];
    const float* Wout = (const float*)d_in[3];
    const float* bout = (const float*)d_in[4];
    float* out = (float*)d_out;

    __half *qkvh, *attnh, *xh, *wqkvT, *woutT;
    cudaGetSymbolAddress((void**)&qkvh,  g_qkvh);
    cudaGetSymbolAddress((void**)&attnh, g_attnh);
    cudaGetSymbolAddress((void**)&xh,    g_xh);
    cudaGetSymbolAddress((void**)&wqkvT, g_wqkvT);
    cudaGetSymbolAddress((void**)&woutT, g_woutT);

    cudaFuncSetAttribute((const void*)gemm_h<true>,
                         cudaFuncAttributeMaxDynamicSharedMemorySize, GEMM_SMEM);
    cudaFuncSetAttribute((const void*)gemm_h<false>,
                         cudaFuncAttributeMaxDynamicSharedMemorySize, GEMM_SMEM);
    cudaFuncSetAttribute((const void*)attn_h,
                         cudaFuncAttributeMaxDynamicSharedMemorySize, ATTN_SMEM);

    // fp16 conversions: x and transposed weights
    cvt_h<<<(M_TOT * D_MODEL) / (256 * 8), 256>>>(x, xh);
    transpose_h<<<dim3((3 * D_MODEL) / 32, D_MODEL / 32), dim3(32, 8)>>>(
        Wqkv, wqkvT, D_MODEL, 3 * D_MODEL);
    transpose_h<<<dim3(D_MODEL / 32, D_MODEL / 32), dim3(32, 8)>>>(
        Wout, woutT, D_MODEL, D_MODEL);

    // GEMM1: qkv = fp16(x @ Wqkv + b)
    gemm_h<true><<<dim3((3 * D_MODEL) / 128, M_TOT / 128), 256, GEMM_SMEM>>>(
        xh, wqkvT, bqkv, qkvh, 3 * D_MODEL, D_MODEL);

    // Attention (fp16 tensor cores)
    attn_h<<<dim3(SEQ / 128, NH, BATCH), 256, ATTN_SMEM>>>(qkvh, attnh);

    // GEMM2: out = attn @ Wout + b (fp32 output)
    gemm_h<false><<<dim3(D_MODEL / 128, M_TOT / 128), 256, GEMM_SMEM>>>(
        attnh, woutT, bout, out, D_MODEL, D_MODEL);
}